// round 8
// baseline (speedup 1.0000x reference)
#include <cuda_runtime.h>
#include <math.h>

#define TOTAL_PTS    172032
#define NBLK         672          // blocks; 128 threads x 2 pts = 256 pts/block
#define BLKS_PER_IMG 84           // 21504 / 256
#define NWPART       (NBLK * 4)   // per-warp partials
#define INF_A        1.0e8f
#define NCLS         20
#define LN2_075      0.5198603854199589f   // 0.75 * ln(2)

__device__ float4   g_part[NWPART];
__device__ unsigned g_count = 0;

typedef unsigned long long u64;

__device__ __forceinline__ u64 pk2(float lo, float hi) {
    u64 r; asm("mov.b64 %0,{%1,%2};" : "=l"(r) : "f"(lo), "f"(hi)); return r;
}
__device__ __forceinline__ void upk2(float& lo, float& hi, u64 v) {
    asm("mov.b64 {%0,%1},%2;" : "=f"(lo), "=f"(hi) : "l"(v));
}
__device__ __forceinline__ float ex2a(float x) { float r; asm("ex2.approx.f32 %0,%1;" : "=f"(r) : "f"(x)); return r; }
__device__ __forceinline__ float lg2a(float x) { float r; asm("lg2.approx.f32 %0,%1;" : "=f"(r) : "f"(x)); return r; }
__device__ __forceinline__ float rcpa(float x) { float r; asm("rcp.approx.f32 %0,%1;" : "=f"(r) : "f"(x)); return r; }
__device__ __forceinline__ u64 mul2(u64 a, u64 b) { u64 r; asm("mul.rn.f32x2 %0,%1,%2;" : "=l"(r) : "l"(a), "l"(b)); return r; }
__device__ __forceinline__ u64 add2(u64 a, u64 b) { u64 r; asm("add.rn.f32x2 %0,%1,%2;" : "=l"(r) : "l"(a), "l"(b)); return r; }
__device__ __forceinline__ u64 fma2(u64 a, u64 b, u64 c) { u64 r; asm("fma.rn.f32x2 %0,%1,%2,%3;" : "=l"(r) : "l"(a), "l"(b), "l"(c)); return r; }

__device__ __forceinline__ float4 warp_red(float4 a) {
    #pragma unroll
    for (int off = 16; off > 0; off >>= 1) {
        a.x += __shfl_down_sync(0xffffffffu, a.x, off);
        a.y += __shfl_down_sync(0xffffffffu, a.y, off);
        a.z += __shfl_down_sync(0xffffffffu, a.z, off);
        a.w += __shfl_down_sync(0xffffffffu, a.w, off);
    }
    return a;
}

__global__ __launch_bounds__(128) void k_fused(
    const float* __restrict__ cls0, const float* __restrict__ cls1, const float* __restrict__ cls2,
    const float* __restrict__ reg0, const float* __restrict__ reg1, const float* __restrict__ reg2,
    const float* __restrict__ ctr0, const float* __restrict__ ctr1, const float* __restrict__ ctr2,
    const float* __restrict__ boxes, const int* __restrict__ labels,
    float* __restrict__ out)
{
    __shared__ float4 sbox[4][32];
    __shared__ float  sarea[4][32];
    __shared__ int    slab[4][32];

    const int tid  = threadIdx.x;
    const int wid  = tid >> 5;
    const int lane = tid & 31;
    const int bid  = blockIdx.x;

    // ---- target-side (batch-major) block-uniform decode ----
    const int b_img = bid / BLKS_PER_IMG;
    const int pblk  = (bid - b_img * BLKS_PER_IMG) << 8;

    int lv, base, Wsh; float s, lmin, lmax;
    if (pblk < 16384)      { lv = 0; base = 0;     Wsh = 7; s = 4.0f;  lmin = -1.0f;  lmax = 64.0f;  }
    else if (pblk < 20480) { lv = 1; base = 16384; Wsh = 6; s = 8.0f;  lmin = 64.0f;  lmax = 128.0f; }
    else                   { lv = 2; base = 20480; Wsh = 5; s = 16.0f; lmin = 128.0f; lmax = INF_A;  }

    const int p0 = pblk + (tid << 1) - base;
    const int hh = p0 >> Wsh;
    const int ww = p0 & ((1 << Wsh) - 1);
    const float x0 = ww * s + 0.5f * s;
    const float y  = hh * s + 0.5f * s;
    const float x1 = x0 + s;

    const int lo_blk = pblk - base;
    const float ymin_blk = (float)(lo_blk >> Wsh) * s + 0.5f * s;
    const float ymax_blk = (float)((lo_blk + 255) >> Wsh) * s + 0.5f * s;

    // ---- boxes + labels load first (feeds cull) ----
    const float4 bb_me = reinterpret_cast<const float4*>(boxes)[b_img * 32 + lane];
    const int    lb_me = labels[b_img * 32 + lane];

    // ---- prediction-side decode + full prefetch (25 x LDG.64 in flight) ----
    const int j0 = bid << 8;
    int HW, b_f, pix;
    const float *cb, *rb, *ob;
    if (j0 < 131072)      { HW = 16384; b_f = j0 >> 14;            pix = j0 & 16383;           cb = cls0; rb = reg0; ob = ctr0; }
    else if (j0 < 163840) { HW = 4096;  b_f = (j0 - 131072) >> 12; pix = (j0 - 131072) & 4095; cb = cls1; rb = reg1; ob = ctr1; }
    else                  { HW = 1024;  b_f = (j0 - 163840) >> 10; pix = (j0 - 163840) & 1023; cb = cls2; rb = reg2; ob = ctr2; }
    pix += (tid << 1);

    const float* cptr = cb + (size_t)(b_f * NCLS) * HW + pix;
    const float* rp   = rb + (size_t)(b_f * 4) * HW + pix;
    const float* op   = ob + (size_t)b_f * HW + pix;

    float2 v[NCLS];
    #pragma unroll
    for (int c = 0; c < NCLS; c++)
        v[c] = *reinterpret_cast<const float2*>(cptr + (size_t)c * HW);
    float2 rg[4];
    #pragma unroll
    for (int k = 0; k < 4; k++)
        rg[k] = *reinterpret_cast<const float2*>(rp + (size_t)k * HW);
    const float2 oc2 = *reinterpret_cast<const float2*>(op);

    // ---- per-warp cull + stable compaction (no block barrier!) ----
    {
        const float bw = bb_me.z - bb_me.x, bh = bb_me.w - bb_me.y;
        bool keep = (bb_me.y < ymax_blk) & (bb_me.w > ymin_blk);
        const float M = fmaxf(bw, bh);
        keep = keep & ((lv == 0) ? (M <= 128.0f) : (M >= ((lv == 1) ? 64.0f : 128.0f)));
        const unsigned bm = __ballot_sync(0xffffffffu, keep);
        if (keep) {
            const int idx = __popc(bm & ((1u << lane) - 1u));   // stable
            sbox[wid][idx]  = bb_me;
            sarea[wid][idx] = bw * bh;
            slab[wid][idx]  = lb_me;
        }
        __syncwarp();
        const int nbox = __popc(bm);

        // ---- box assignment over this warp's survivors ----
        float best[2] = {INF_A, INF_A};
        int   bi[2]   = {0, 0};
        for (int m = 0; m < nbox; m++) {
            const float4 bb = sbox[wid][m];
            const float a   = sarea[wid][m];
            const float tt   = y - bb.y;
            const float bo   = bb.w - y;
            const float mntb = fminf(tt, bo);
            const float mxtb = fmaxf(tt, bo);
            #pragma unroll
            for (int i = 0; i < 2; i++) {
                const float xi = i ? x1 : x0;
                const float l  = xi - bb.x;
                const float r  = bb.z - xi;
                const float mn = fminf(mntb, fminf(l, r));
                const float mx = fmaxf(mxtb, fmaxf(l, r));
                const bool ok = (mn > 0.0f) & (mx >= lmin) & (mx <= lmax);
                if (ok & (a < best[i])) { best[i] = a; bi[i] = m; }
            }
        }
        bool pos[2]; int lab[2];
        #pragma unroll
        for (int i = 0; i < 2; i++) {
            pos[i] = best[i] < INF_A;
            lab[i] = pos[i] ? slab[wid][bi[i]] : -1;
        }

        // ---- focal loss: packed f32x2 over the 2 points ----
        const u64 kONE = pk2(1.0f, 1.0f);
        const u64 kM1  = pk2(-1.0f, -1.0f);
        const u64 kL2E = pk2(1.4426950408889634f, 1.4426950408889634f);
        u64 fsum2 = pk2(0.0f, 0.0f);
        float mxa = -INF_A, mxb = -INF_A;
        #pragma unroll
        for (int c = 0; c < NCLS; c++) {
            const float2 vc = v[c];
            mxa = fmaxf(mxa, vc.x);
            mxb = fmaxf(mxb, vc.y);
            const u64 xv = pk2(vc.x, vc.y);
            const u64 z  = mul2(xv, kL2E);
            float z0, z1; upk2(z0, z1, z);
            const u64 E  = pk2(ex2a(z0), ex2a(z1));
            const u64 u  = add2(E, kONE);
            float u0, u1; upk2(u0, u1, u);
            const u64 rc = pk2(rcpa(u0), rcpa(u1));
            const u64 pp = fma2(rc, kM1, kONE);      // sigmoid = 1 - 1/(1+E)
            const u64 sq = mul2(pp, pp);
            const u64 L  = pk2(lg2a(u0), lg2a(u1));  // log2(1+E)
            fsum2 = fma2(L, sq, fsum2);
        }
        float fs0, fs1; upk2(fs0, fs1, fsum2);
        const float fsum[2] = {fs0, fs1};
        const float mx2[2]  = {mxa, mxb};

        // ---- per-point epilogue ----
        float4 acc = make_float4(0.f, 0.f, 0.f, 0.f);
        #pragma unroll
        for (int i = 0; i < 2; i++) {
            float f = fsum[i] * LN2_075;
            if (pos[i]) {
                // focal correction for the hit class (reload logit; cache hit)
                const float xl = cptr[(size_t)lab[i] * HW + i];
                const float E  = __expf(xl);
                const float u  = 1.0f + E;
                const float rc = rcpa(u);
                const float pp = E * rc;
                const float sp = __logf(u);
                f += 0.25f * (sp - xl) * rc * rc - 0.75f * sp * pp * pp;
                acc.x += f;
                acc.w += 1.0f;

                const float4 wb = sbox[wid][bi[i]];
                const float xi = i ? x1 : x0;
                const float tl = xi - wb.x, tt = y - wb.y, tr = wb.z - xi, tb = wb.w - y;
                const float lrmin = fminf(tl, tr), lrmax = fmaxf(tl, tr);
                const float tbmin = fminf(tt, tb), tbmax = fmaxf(tt, tb);
                const float ratio = __fdividef(lrmin, fmaxf(lrmax, 1e-12f)) *
                                    __fdividef(tbmin, fmaxf(tbmax, 1e-12f));
                const float ctr_t = sqrtf(fmaxf(ratio, 0.0f));

                const float pl  = i ? rg[0].y : rg[0].x;
                const float pt2 = i ? rg[1].y : rg[1].x;
                const float pr  = i ? rg[2].y : rg[2].x;
                const float pb  = i ? rg[3].y : rg[3].x;
                const float t_area = (tl + tr) * (tt + tb);
                const float p_area = (pl + pr) * (pt2 + pb);
                const float w_i = fminf(pl, tl) + fminf(pr, tr);
                const float h_i = fminf(pb, tb) + fminf(pt2, tt);
                const float a_i = w_i * h_i;
                const float a_u = t_area + p_area - a_i;
                const float iou = __fdividef(a_i + 1.0f, a_u + 1.0f);
                const float gw  = fmaxf(pl, tl) + fmaxf(pr, tr);
                const float gh  = fmaxf(pb, tb) + fmaxf(pt2, tt);
                const float ac  = gw * gh;
                acc.y += (1.0f - (iou - __fdividef(ac - a_u, ac))) * ctr_t;

                const float oc = i ? oc2.y : oc2.x;
                const float e2 = __expf(-fabsf(oc));
                acc.z += fmaxf(oc, 0.0f) + __logf(1.0f + e2) - oc * ctr_t;
            } else {
                // ignore weight: max sigmoid > 0.3  <=>  max logit > ln(3/7)
                if (mx2[i] <= -0.8472978603872037f) acc.x += f;
            }
        }

        // ---- warp reduction -> per-warp partial (no block sync) ----
        acc = warp_red(acc);
        int iswin = 0;
        if (lane == 0) {
            g_part[bid * 4 + wid] = acc;
            __threadfence();
            const unsigned old = atomicAdd(&g_count, 1u);
            iswin = (old == (unsigned)(NWPART - 1));
        }
        iswin = __shfl_sync(0xffffffffu, iswin, 0);
        if (!iswin) return;
    }

    // ---- last warp finalizes (84 float4 per lane) ----
    __threadfence();
    float4 a = make_float4(0.f, 0.f, 0.f, 0.f);
    for (int i = lane; i < NWPART; i += 32) {
        const float4* pp = &g_part[i];
        float4 vv;
        asm volatile("ld.global.cg.v4.f32 {%0,%1,%2,%3}, [%4];"
                     : "=f"(vv.x), "=f"(vv.y), "=f"(vv.z), "=f"(vv.w) : "l"(pp));
        a.x += vv.x; a.y += vv.y; a.z += vv.z; a.w += vv.w;
    }
    a = warp_red(a);
    if (lane == 0) {
        const float inv = __fdividef(1.0f, fmaxf(a.w, 1.0f));
        out[0] = a.x * inv;
        out[1] = a.y * inv;
        out[2] = a.z * inv;
        g_count = 0;   // reset for next graph replay
    }
}

extern "C" void kernel_launch(void* const* d_in, const int* in_sizes, int n_in,
                              void* d_out, int out_size) {
    const float *cls0, *cls1, *cls2, *reg0, *reg1, *reg2, *ctr0, *ctr1, *ctr2;
    if (in_sizes[1] == 655360) {   // reference-signature order
        cls0 = (const float*)d_in[0]; cls1 = (const float*)d_in[1]; cls2 = (const float*)d_in[2];
        reg0 = (const float*)d_in[3]; reg1 = (const float*)d_in[4]; reg2 = (const float*)d_in[5];
        ctr0 = (const float*)d_in[6]; ctr1 = (const float*)d_in[7]; ctr2 = (const float*)d_in[8];
    } else {                       // setup_inputs dict order
        cls0 = (const float*)d_in[0]; reg0 = (const float*)d_in[1]; ctr0 = (const float*)d_in[2];
        cls1 = (const float*)d_in[3]; reg1 = (const float*)d_in[4]; ctr1 = (const float*)d_in[5];
        cls2 = (const float*)d_in[6]; reg2 = (const float*)d_in[7]; ctr2 = (const float*)d_in[8];
    }
    const float* boxes  = (const float*)d_in[9];
    const int*   labels = (const int*)d_in[10];

    k_fused<<<NBLK, 128>>>(cls0, cls1, cls2, reg0, reg1, reg2,
                           ctr0, ctr1, ctr2, boxes, labels, (float*)d_out);
}

// round 10
// speedup vs baseline: 1.4353x; 1.4353x over previous
#include <cuda_runtime.h>
#include <math.h>

#define TOTAL_PTS    172032
#define NBLK         672          // blocks; 128 threads x 2 pts = 256 pts/block
#define BLKS_PER_IMG 84           // 21504 / 256
#define INF_A        1.0e8f
#define NCLS         20
#define LN2_075      0.5198603854199589f   // 0.75 * ln(2)

__device__ float4   g_part[NBLK];
__device__ unsigned g_count = 0;

__device__ __forceinline__ float4 warp_red(float4 a) {
    #pragma unroll
    for (int off = 16; off > 0; off >>= 1) {
        a.x += __shfl_down_sync(0xffffffffu, a.x, off);
        a.y += __shfl_down_sync(0xffffffffu, a.y, off);
        a.z += __shfl_down_sync(0xffffffffu, a.z, off);
        a.w += __shfl_down_sync(0xffffffffu, a.w, off);
    }
    return a;
}

// Templated ONLY on the prediction-side level Q (compile-time HW for loads).
// Target-side level data (s, lmin, lmax, lv_t, geometry) passed at runtime —
// the two flattenings disagree per block, so they must stay independent.
template<int Q>
__device__ __forceinline__ float4 body(
    const int tid, const int bid,
    // target-side runtime values
    const int b_img, const int lv_t, const float s, const float lmin, const float lmax,
    const float x0, const float x1, const float y,
    const float ymin_blk, const float ymax_blk,
    // prediction-side tensors for level Q
    const float* __restrict__ cb, const float* __restrict__ rb, const float* __restrict__ ob,
    const float* __restrict__ boxes, const int* __restrict__ labels,
    float4* sbox, float* sarea, int* slab, int* s_n)
{
    constexpr int HW   = (Q == 0) ? 16384 : (Q == 1) ? 4096 : 1024;
    constexpr int QSH  = (Q == 0) ? 14 : (Q == 1) ? 12 : 10;      // log2(HW)
    constexpr int JOFF = (Q == 0) ? 0 : (Q == 1) ? 131072 : 163840;

    // ---- prediction-side decode: jl >= 0 guaranteed by dispatch on j0 ----
    const int jl  = (bid << 8) - JOFF;
    const int b_f = jl >> QSH;
    const int pix = (jl & (HW - 1)) + (tid << 1);

    const float* cptr = cb + (size_t)(b_f * NCLS) * HW + pix;

    // ---- prefetch 20 cls planes (immediate-offset LDG.64, all in flight) ----
    float2 v[NCLS];
    #pragma unroll
    for (int c = 0; c < NCLS; c++)
        v[c] = *reinterpret_cast<const float2*>(cptr + c * HW);

    // ---- box cull + stable compaction (warp 0; lv_t is warp-uniform) ----
    if (tid < 32) {
        const float4 bb = reinterpret_cast<const float4*>(boxes)[b_img * 32 + tid];
        const float bw = bb.z - bb.x, bh = bb.w - bb.y;
        bool keep = (bb.y < ymax_blk) & (bb.w > ymin_blk);   // y-overlap
        if (lv_t == 0)      keep = keep & (bw <= 128.0f) & (bh <= 128.0f);
        else if (lv_t == 1) keep = keep & ((bw >= 64.0f)  | (bh >= 64.0f));
        else                keep = keep & ((bw >= 128.0f) | (bh >= 128.0f));
        const unsigned m = __ballot_sync(0xffffffffu, keep);
        if (keep) {
            const int idx = __popc(m & ((1u << tid) - 1u));   // stable order
            sbox[idx]  = bb;
            sarea[idx] = bw * bh;
            slab[idx]  = labels[b_img * 32 + tid];
        }
        if (tid == 0) *s_n = __popc(m);
    }
    __syncthreads();
    const int nbox = *s_n;

    // ---- box assignment over compacted survivors (2 points, shared y) ----
    float best[2] = {INF_A, INF_A};
    int   bi[2]   = {0, 0};
    for (int m = 0; m < nbox; m++) {
        const float4 bb = sbox[m];
        const float a   = sarea[m];
        const float tt   = y - bb.y;
        const float bo   = bb.w - y;
        const float mntb = fminf(tt, bo);
        const float mxtb = fmaxf(tt, bo);
        #pragma unroll
        for (int i = 0; i < 2; i++) {
            const float xi = i ? x1 : x0;
            const float l  = xi - bb.x;
            const float r  = bb.z - xi;
            const float mn = fminf(mntb, fminf(l, r));
            const float mx = fmaxf(mxtb, fmaxf(l, r));
            const bool ok = (mn > 0.0f) & (mx >= lmin) & (mx <= lmax);
            if (ok & (a < best[i])) { best[i] = a; bi[i] = m; }
        }
    }
    bool pos[2]; int lab[2];
    #pragma unroll
    for (int i = 0; i < 2; i++) {
        pos[i] = best[i] < INF_A;
        lab[i] = pos[i] ? slab[bi[i]] : -1;
    }

    // ---- deferred reg/ctr loads: neg points contribute exactly 0 to bbox/ctr.
    //      Issued here so the focal MUFU block hides their latency. ----
    const float* rp = rb + (size_t)(b_f * 4) * HW + pix;
    const float* op = ob + (size_t)b_f * HW + pix;
    float2 rg[4] = {{0.f,0.f},{0.f,0.f},{0.f,0.f},{0.f,0.f}};
    float2 oc2   = {0.f, 0.f};
    if (pos[0] | pos[1]) {
        #pragma unroll
        for (int k = 0; k < 4; k++)
            rg[k] = *reinterpret_cast<const float2*>(rp + k * HW);
        oc2 = *reinterpret_cast<const float2*>(op);
    }

    // ---- focal loss on prefetched registers ----
    float fsum[2] = {0.f, 0.f};
    float mx2[2]  = {-INF_A, -INF_A};
    #pragma unroll
    for (int c = 0; c < NCLS; c++) {
        const float xv[2] = {v[c].x, v[c].y};
        #pragma unroll
        for (int i = 0; i < 2; i++) {
            const float xx = xv[i];
            mx2[i] = fmaxf(mx2[i], xx);
            const float E  = __expf(xx);
            const float u  = 1.0f + E;
            const float rc = __fdividef(1.0f, u);
            const float pp = E * rc;
            fsum[i] += __log2f(u) * (pp * pp);   // scaled by 0.75*ln2 after loop
        }
    }

    // ---- per-point epilogue ----
    float4 acc = make_float4(0.f, 0.f, 0.f, 0.f);
    #pragma unroll
    for (int i = 0; i < 2; i++) {
        float f = fsum[i] * LN2_075;
        if (pos[i]) {
            // focal correction for the hit class (reload logit; cache hit)
            const float xl = cptr[lab[i] * HW + i];
            const float E  = __expf(xl);
            const float u  = 1.0f + E;
            const float rc = __fdividef(1.0f, u);
            const float pp = E * rc;
            const float sp = __logf(u);
            f += 0.25f * (sp - xl) * rc * rc - 0.75f * sp * pp * pp;
            acc.x += f;
            acc.w += 1.0f;

            // targets for winning box
            const float4 wb = sbox[bi[i]];
            const float xi = i ? x1 : x0;
            const float tl = xi - wb.x, tt = y - wb.y, tr = wb.z - xi, tb = wb.w - y;
            const float lrmin = fminf(tl, tr), lrmax = fmaxf(tl, tr);
            const float tbmin = fminf(tt, tb), tbmax = fmaxf(tt, tb);
            const float ratio = __fdividef(lrmin, fmaxf(lrmax, 1e-12f)) *
                                __fdividef(tbmin, fmaxf(tbmax, 1e-12f));
            const float ctr_t = sqrtf(fmaxf(ratio, 0.0f));

            // GIoU
            const float pl  = i ? rg[0].y : rg[0].x;
            const float pt2 = i ? rg[1].y : rg[1].x;
            const float pr  = i ? rg[2].y : rg[2].x;
            const float pb  = i ? rg[3].y : rg[3].x;
            const float t_area = (tl + tr) * (tt + tb);
            const float p_area = (pl + pr) * (pt2 + pb);
            const float w_i = fminf(pl, tl) + fminf(pr, tr);
            const float h_i = fminf(pb, tb) + fminf(pt2, tt);
            const float a_i = w_i * h_i;
            const float a_u = t_area + p_area - a_i;
            const float iou = __fdividef(a_i + 1.0f, a_u + 1.0f);
            const float gw  = fmaxf(pl, tl) + fmaxf(pr, tr);
            const float gh  = fmaxf(pb, tb) + fmaxf(pt2, tt);
            const float ac  = gw * gh;
            acc.y += (1.0f - (iou - __fdividef(ac - a_u, ac))) * ctr_t;

            // centerness BCE
            const float oc = i ? oc2.y : oc2.x;
            const float e2 = __expf(-fabsf(oc));
            acc.z += fmaxf(oc, 0.0f) + __logf(1.0f + e2) - oc * ctr_t;
        } else {
            // ignore weight: max sigmoid > 0.3  <=>  max logit > ln(3/7)
            if (mx2[i] <= -0.8472978603872037f) acc.x += f;
        }
    }
    return acc;
}

__global__ __launch_bounds__(128) void k_fused(
    const float* __restrict__ cls0, const float* __restrict__ cls1, const float* __restrict__ cls2,
    const float* __restrict__ reg0, const float* __restrict__ reg1, const float* __restrict__ reg2,
    const float* __restrict__ ctr0, const float* __restrict__ ctr1, const float* __restrict__ ctr2,
    const float* __restrict__ boxes, const int* __restrict__ labels,
    float* __restrict__ out)
{
    __shared__ float4 sbox[32];
    __shared__ float  sarea[32];
    __shared__ int    slab[32];
    __shared__ int    s_n;
    __shared__ float4 sw[4];
    __shared__ bool   s_last;

    const int tid = threadIdx.x;
    const int bid = blockIdx.x;

    // ---- target-side (batch-major) decode — INDEPENDENT of prediction side ----
    const int b_img = bid / BLKS_PER_IMG;
    const int pblk  = (bid - b_img * BLKS_PER_IMG) << 8;

    int lv_t, base, Wsh; float s, lmin, lmax;
    if (pblk < 16384)      { lv_t = 0; base = 0;     Wsh = 7; s = 4.0f;  lmin = -1.0f;  lmax = 64.0f;  }
    else if (pblk < 20480) { lv_t = 1; base = 16384; Wsh = 6; s = 8.0f;  lmin = 64.0f;  lmax = 128.0f; }
    else                   { lv_t = 2; base = 20480; Wsh = 5; s = 16.0f; lmin = 128.0f; lmax = INF_A;  }

    const int p0 = pblk + (tid << 1) - base;
    const int hh = p0 >> Wsh;
    const int ww = p0 & ((1 << Wsh) - 1);
    const float x0 = ww * s + 0.5f * s;
    const float y  = hh * s + 0.5f * s;
    const float x1 = x0 + s;

    const int lo_blk = pblk - base;
    const float ymin_blk = (float)(lo_blk >> Wsh) * s + 0.5f * s;
    const float ymax_blk = (float)((lo_blk + 255) >> Wsh) * s + 0.5f * s;

    // ---- dispatch on PREDICTION-side level (j0 thresholds) ----
    const int j0 = bid << 8;
    float4 acc;
    if (j0 < 131072)
        acc = body<0>(tid, bid, b_img, lv_t, s, lmin, lmax, x0, x1, y, ymin_blk, ymax_blk,
                      cls0, reg0, ctr0, boxes, labels, sbox, sarea, slab, &s_n);
    else if (j0 < 163840)
        acc = body<1>(tid, bid, b_img, lv_t, s, lmin, lmax, x0, x1, y, ymin_blk, ymax_blk,
                      cls1, reg1, ctr1, boxes, labels, sbox, sarea, slab, &s_n);
    else
        acc = body<2>(tid, bid, b_img, lv_t, s, lmin, lmax, x0, x1, y, ymin_blk, ymax_blk,
                      cls2, reg2, ctr2, boxes, labels, sbox, sarea, slab, &s_n);

    // ---- block reduction (4 warps) -> per-block partial ----
    acc = warp_red(acc);
    if ((tid & 31) == 0) sw[tid >> 5] = acc;
    __syncthreads();
    if (tid == 0) {
        float4 a0 = sw[0], a1 = sw[1], a2 = sw[2], a3 = sw[3];
        g_part[bid] = make_float4(a0.x + a1.x + a2.x + a3.x,
                                  a0.y + a1.y + a2.y + a3.y,
                                  a0.z + a1.z + a2.z + a3.z,
                                  a0.w + a1.w + a2.w + a3.w);
    }

    // ---- last block finalizes ----
    if (tid == 0) {
        __threadfence();
        unsigned old = atomicAdd(&g_count, 1u);
        s_last = (old == (unsigned)(gridDim.x - 1));
    }
    __syncthreads();
    if (!s_last) return;
    __threadfence();

    float4 a = make_float4(0.f, 0.f, 0.f, 0.f);
    for (int i = tid; i < NBLK; i += 128) {
        const float4* pp = &g_part[i];
        float4 vv;
        asm volatile("ld.global.cg.v4.f32 {%0,%1,%2,%3}, [%4];"
                     : "=f"(vv.x), "=f"(vv.y), "=f"(vv.z), "=f"(vv.w) : "l"(pp));
        a.x += vv.x; a.y += vv.y; a.z += vv.z; a.w += vv.w;
    }
    a = warp_red(a);
    if ((tid & 31) == 0) sw[tid >> 5] = a;
    __syncthreads();
    if (tid == 0) {
        float4 t0 = sw[0], t1 = sw[1], t2 = sw[2], t3 = sw[3];
        float sx = t0.x + t1.x + t2.x + t3.x;
        float sy = t0.y + t1.y + t2.y + t3.y;
        float sz = t0.z + t1.z + t2.z + t3.z;
        float np = t0.w + t1.w + t2.w + t3.w;
        float inv = __fdividef(1.0f, fmaxf(np, 1.0f));
        out[0] = sx * inv;
        out[1] = sy * inv;
        out[2] = sz * inv;
        g_count = 0;   // reset for next graph replay
    }
}

extern "C" void kernel_launch(void* const* d_in, const int* in_sizes, int n_in,
                              void* d_out, int out_size) {
    const float *cls0, *cls1, *cls2, *reg0, *reg1, *reg2, *ctr0, *ctr1, *ctr2;
    if (in_sizes[1] == 655360) {   // reference-signature order
        cls0 = (const float*)d_in[0]; cls1 = (const float*)d_in[1]; cls2 = (const float*)d_in[2];
        reg0 = (const float*)d_in[3]; reg1 = (const float*)d_in[4]; reg2 = (const float*)d_in[5];
        ctr0 = (const float*)d_in[6]; ctr1 = (const float*)d_in[7]; ctr2 = (const float*)d_in[8];
    } else {                       // setup_inputs dict order
        cls0 = (const float*)d_in[0]; reg0 = (const float*)d_in[1]; ctr0 = (const float*)d_in[2];
        cls1 = (const float*)d_in[3]; reg1 = (const float*)d_in[4]; ctr1 = (const float*)d_in[5];
        cls2 = (const float*)d_in[6]; reg2 = (const float*)d_in[7]; ctr2 = (const float*)d_in[8];
    }
    const float* boxes  = (const float*)d_in[9];
    const int*   labels = (const int*)d_in[10];

    k_fused<<<NBLK, 128>>>(cls0, cls1, cls2, reg0, reg1, reg2,
                           ctr0, ctr1, ctr2, boxes, labels, (float*)d_out);
}

// round 11
// speedup vs baseline: 1.4389x; 1.0025x over previous
#include <cuda_runtime.h>
#include <math.h>

#define TOTAL_PTS    172032
#define NBLK         672          // blocks; 256 threads x 1 pt = 256 pts/block
#define BLKS_PER_IMG 84           // 21504 / 256
#define INF_A        1.0e8f
#define NCLS         20
#define LN2_075      0.5198603854199589f   // 0.75 * ln(2)

__device__ float4   g_part[NBLK];
__device__ unsigned g_count = 0;

__device__ __forceinline__ float4 warp_red(float4 a) {
    #pragma unroll
    for (int off = 16; off > 0; off >>= 1) {
        a.x += __shfl_down_sync(0xffffffffu, a.x, off);
        a.y += __shfl_down_sync(0xffffffffu, a.y, off);
        a.z += __shfl_down_sync(0xffffffffu, a.z, off);
        a.w += __shfl_down_sync(0xffffffffu, a.w, off);
    }
    return a;
}

// Templated ONLY on the prediction-side level Q (compile-time HW for loads).
// Target-side level data stays runtime — the two flattenings disagree per block.
template<int Q>
__device__ __forceinline__ float4 body(
    const int tid, const int bid,
    const int b_img, const int lv_t, const float lmin, const float lmax,
    const float x, const float y,
    const float ymin_blk, const float ymax_blk,
    const float* __restrict__ cb, const float* __restrict__ rb, const float* __restrict__ ob,
    const float* __restrict__ boxes, const int* __restrict__ labels,
    float4* sbox, float* sarea, int* slab, int* s_n)
{
    constexpr int HW   = (Q == 0) ? 16384 : (Q == 1) ? 4096 : 1024;
    constexpr int QSH  = (Q == 0) ? 14 : (Q == 1) ? 12 : 10;      // log2(HW)
    constexpr int JOFF = (Q == 0) ? 0 : (Q == 1) ? 131072 : 163840;

    // ---- prediction-side decode: jl >= 0 guaranteed by dispatch on j0 ----
    const int jl  = (bid << 8) - JOFF;
    const int b_f = jl >> QSH;
    const int pix = (jl & (HW - 1)) + tid;

    const float* cptr = cb + (size_t)(b_f * NCLS) * HW + pix;

    // ---- prefetch 20 cls planes (immediate-offset LDG.32, all in flight) ----
    float v[NCLS];
    #pragma unroll
    for (int c = 0; c < NCLS; c++)
        v[c] = cptr[c * HW];

    // ---- box cull + stable compaction (warp 0; lv_t warp-uniform) ----
    if (tid < 32) {
        const float4 bb = reinterpret_cast<const float4*>(boxes)[b_img * 32 + tid];
        const float bw = bb.z - bb.x, bh = bb.w - bb.y;
        bool keep = (bb.y < ymax_blk) & (bb.w > ymin_blk);   // y-overlap
        if (lv_t == 0)      keep = keep & (bw <= 128.0f) & (bh <= 128.0f);
        else if (lv_t == 1) keep = keep & ((bw >= 64.0f)  | (bh >= 64.0f));
        else                keep = keep & ((bw >= 128.0f) | (bh >= 128.0f));
        const unsigned m = __ballot_sync(0xffffffffu, keep);
        if (keep) {
            const int idx = __popc(m & ((1u << tid) - 1u));   // stable order
            sbox[idx]  = bb;
            sarea[idx] = bw * bh;
            slab[idx]  = labels[b_img * 32 + tid];
        }
        if (tid == 0) *s_n = __popc(m);
    }
    __syncthreads();
    const int nbox = *s_n;

    // ---- box assignment over compacted survivors ----
    float best = INF_A;
    int   bi   = 0;
    for (int m = 0; m < nbox; m++) {
        const float4 bb = sbox[m];
        const float l  = x - bb.x;
        const float t  = y - bb.y;
        const float r  = bb.z - x;
        const float bo = bb.w - y;
        const float mn = fminf(fminf(l, t), fminf(r, bo));
        const float mx = fmaxf(fmaxf(l, t), fmaxf(r, bo));
        const bool ok = (mn > 0.0f) & (mx >= lmin) & (mx <= lmax);
        const float a = sarea[m];
        if (ok & (a < best)) { best = a; bi = m; }
    }
    const bool pos   = best < INF_A;
    const int  label = pos ? slab[bi] : -1;

    // ---- deferred reg/ctr loads: neg contributes exactly 0 to bbox/ctr.
    //      Issued here so the focal MUFU block hides their latency. ----
    const float* rp = rb + (size_t)(b_f * 4) * HW + pix;
    const float* op = ob + (size_t)b_f * HW + pix;
    float rg[4] = {0.f, 0.f, 0.f, 0.f};
    float oc    = 0.f;
    if (pos) {
        #pragma unroll
        for (int k = 0; k < 4; k++)
            rg[k] = rp[k * HW];
        oc = *op;
    }

    // ---- focal loss on prefetched registers ----
    float fsum = 0.0f;
    float maxx = -INF_A;
    #pragma unroll
    for (int c = 0; c < NCLS; c++) {
        const float xx = v[c];
        maxx = fmaxf(maxx, xx);
        const float E  = __expf(xx);
        const float u  = 1.0f + E;
        const float rc = __fdividef(1.0f, u);
        const float pp = E * rc;
        fsum += __log2f(u) * (pp * pp);   // scaled by 0.75*ln2 after loop
    }

    // ---- epilogue ----
    float4 acc = make_float4(0.f, 0.f, 0.f, 0.f);
    float f = fsum * LN2_075;
    if (pos) {
        // focal correction for the hit class (reload logit; cache hit)
        const float xl = cptr[label * HW];
        const float E  = __expf(xl);
        const float u  = 1.0f + E;
        const float rc = __fdividef(1.0f, u);
        const float pp = E * rc;
        const float sp = __logf(u);
        f += 0.25f * (sp - xl) * rc * rc - 0.75f * sp * pp * pp;
        acc.x = f;
        acc.w = 1.0f;

        // targets for winning box
        const float4 wb = sbox[bi];
        const float tl = x - wb.x, tt = y - wb.y, tr = wb.z - x, tb = wb.w - y;
        const float lrmin = fminf(tl, tr), lrmax = fmaxf(tl, tr);
        const float tbmin = fminf(tt, tb), tbmax = fmaxf(tt, tb);
        const float ratio = __fdividef(lrmin, fmaxf(lrmax, 1e-12f)) *
                            __fdividef(tbmin, fmaxf(tbmax, 1e-12f));
        const float ctr_t = sqrtf(fmaxf(ratio, 0.0f));

        // GIoU
        const float pl  = rg[0];
        const float pt2 = rg[1];
        const float pr  = rg[2];
        const float pb  = rg[3];
        const float t_area = (tl + tr) * (tt + tb);
        const float p_area = (pl + pr) * (pt2 + pb);
        const float w_i = fminf(pl, tl) + fminf(pr, tr);
        const float h_i = fminf(pb, tb) + fminf(pt2, tt);
        const float a_i = w_i * h_i;
        const float a_u = t_area + p_area - a_i;
        const float iou = __fdividef(a_i + 1.0f, a_u + 1.0f);
        const float gw  = fmaxf(pl, tl) + fmaxf(pr, tr);
        const float gh  = fmaxf(pb, tb) + fmaxf(pt2, tt);
        const float ac  = gw * gh;
        acc.y = (1.0f - (iou - __fdividef(ac - a_u, ac))) * ctr_t;

        // centerness BCE
        const float e2 = __expf(-fabsf(oc));
        acc.z = fmaxf(oc, 0.0f) + __logf(1.0f + e2) - oc * ctr_t;
    } else {
        // ignore weight: max sigmoid > 0.3  <=>  max logit > ln(3/7)
        if (maxx <= -0.8472978603872037f) acc.x = f;
    }
    return acc;
}

__global__ __launch_bounds__(256) void k_fused(
    const float* __restrict__ cls0, const float* __restrict__ cls1, const float* __restrict__ cls2,
    const float* __restrict__ reg0, const float* __restrict__ reg1, const float* __restrict__ reg2,
    const float* __restrict__ ctr0, const float* __restrict__ ctr1, const float* __restrict__ ctr2,
    const float* __restrict__ boxes, const int* __restrict__ labels,
    float* __restrict__ out)
{
    __shared__ float4 sbox[32];
    __shared__ float  sarea[32];
    __shared__ int    slab[32];
    __shared__ int    s_n;
    __shared__ float4 sw[8];
    __shared__ bool   s_last;

    const int tid = threadIdx.x;
    const int bid = blockIdx.x;

    // ---- target-side (batch-major) decode — INDEPENDENT of prediction side ----
    const int b_img = bid / BLKS_PER_IMG;
    const int pblk  = (bid - b_img * BLKS_PER_IMG) << 8;

    int lv_t, base, Wsh; float s, lmin, lmax;
    if (pblk < 16384)      { lv_t = 0; base = 0;     Wsh = 7; s = 4.0f;  lmin = -1.0f;  lmax = 64.0f;  }
    else if (pblk < 20480) { lv_t = 1; base = 16384; Wsh = 6; s = 8.0f;  lmin = 64.0f;  lmax = 128.0f; }
    else                   { lv_t = 2; base = 20480; Wsh = 5; s = 16.0f; lmin = 128.0f; lmax = INF_A;  }

    const int p0 = pblk + tid - base;
    const int hh = p0 >> Wsh;
    const int ww = p0 & ((1 << Wsh) - 1);
    const float x = ww * s + 0.5f * s;
    const float y = hh * s + 0.5f * s;

    const int lo_blk = pblk - base;
    const float ymin_blk = (float)(lo_blk >> Wsh) * s + 0.5f * s;
    const float ymax_blk = (float)((lo_blk + 255) >> Wsh) * s + 0.5f * s;

    // ---- dispatch on PREDICTION-side level (j0 thresholds) ----
    const int j0 = bid << 8;
    float4 acc;
    if (j0 < 131072)
        acc = body<0>(tid, bid, b_img, lv_t, lmin, lmax, x, y, ymin_blk, ymax_blk,
                      cls0, reg0, ctr0, boxes, labels, sbox, sarea, slab, &s_n);
    else if (j0 < 163840)
        acc = body<1>(tid, bid, b_img, lv_t, lmin, lmax, x, y, ymin_blk, ymax_blk,
                      cls1, reg1, ctr1, boxes, labels, sbox, sarea, slab, &s_n);
    else
        acc = body<2>(tid, bid, b_img, lv_t, lmin, lmax, x, y, ymin_blk, ymax_blk,
                      cls2, reg2, ctr2, boxes, labels, sbox, sarea, slab, &s_n);

    // ---- block reduction (8 warps) -> per-block partial ----
    acc = warp_red(acc);
    if ((tid & 31) == 0) sw[tid >> 5] = acc;
    __syncthreads();
    if (tid < 32) {
        float4 a = (tid < 8) ? sw[tid] : make_float4(0.f, 0.f, 0.f, 0.f);
        #pragma unroll
        for (int off = 4; off > 0; off >>= 1) {
            a.x += __shfl_down_sync(0xffffffffu, a.x, off);
            a.y += __shfl_down_sync(0xffffffffu, a.y, off);
            a.z += __shfl_down_sync(0xffffffffu, a.z, off);
            a.w += __shfl_down_sync(0xffffffffu, a.w, off);
        }
        if (tid == 0) g_part[bid] = a;
    }

    // ---- last block finalizes ----
    if (tid == 0) {
        __threadfence();
        unsigned old = atomicAdd(&g_count, 1u);
        s_last = (old == (unsigned)(gridDim.x - 1));
    }
    __syncthreads();
    if (!s_last) return;
    __threadfence();

    float4 a = make_float4(0.f, 0.f, 0.f, 0.f);
    for (int i = tid; i < NBLK; i += 256) {
        const float4* pp = &g_part[i];
        float4 vv;
        asm volatile("ld.global.cg.v4.f32 {%0,%1,%2,%3}, [%4];"
                     : "=f"(vv.x), "=f"(vv.y), "=f"(vv.z), "=f"(vv.w) : "l"(pp));
        a.x += vv.x; a.y += vv.y; a.z += vv.z; a.w += vv.w;
    }
    a = warp_red(a);
    if ((tid & 31) == 0) sw[tid >> 5] = a;
    __syncthreads();
    if (tid == 0) {
        float sx = 0.f, sy = 0.f, sz = 0.f, np = 0.f;
        #pragma unroll
        for (int k = 0; k < 8; k++) { sx += sw[k].x; sy += sw[k].y; sz += sw[k].z; np += sw[k].w; }
        const float inv = __fdividef(1.0f, fmaxf(np, 1.0f));
        out[0] = sx * inv;
        out[1] = sy * inv;
        out[2] = sz * inv;
        g_count = 0;   // reset for next graph replay
    }
}

extern "C" void kernel_launch(void* const* d_in, const int* in_sizes, int n_in,
                              void* d_out, int out_size) {
    const float *cls0, *cls1, *cls2, *reg0, *reg1, *reg2, *ctr0, *ctr1, *ctr2;
    if (in_sizes[1] == 655360) {   // reference-signature order
        cls0 = (const float*)d_in[0]; cls1 = (const float*)d_in[1]; cls2 = (const float*)d_in[2];
        reg0 = (const float*)d_in[3]; reg1 = (const float*)d_in[4]; reg2 = (const float*)d_in[5];
        ctr0 = (const float*)d_in[6]; ctr1 = (const float*)d_in[7]; ctr2 = (const float*)d_in[8];
    } else {                       // setup_inputs dict order
        cls0 = (const float*)d_in[0]; reg0 = (const float*)d_in[1]; ctr0 = (const float*)d_in[2];
        cls1 = (const float*)d_in[3]; reg1 = (const float*)d_in[4]; ctr1 = (const float*)d_in[5];
        cls2 = (const float*)d_in[6]; reg2 = (const float*)d_in[7]; ctr2 = (const float*)d_in[8];
    }
    const float* boxes  = (const float*)d_in[9];
    const int*   labels = (const int*)d_in[10];

    k_fused<<<NBLK, 256>>>(cls0, cls1, cls2, reg0, reg1, reg2,
                           ctr0, ctr1, ctr2, boxes, labels, (float*)d_out);
}

// round 12
// speedup vs baseline: 1.5065x; 1.0470x over previous
#include <cuda_runtime.h>
#include <math.h>

#define TOTAL_PTS    172032
#define NBLK         672          // blocks; 256 threads x 1 pt = 256 pts/block
#define BLKS_PER_IMG 84           // 21504 / 256
#define INF_A        1.0e8f
#define NCLS         20
#define LN2_075      0.5198603854199589f     // 0.75 * ln(2)
#define W_THRESH     -0.8472978603872037f    // ln(0.3/0.7)

__device__ float4   g_part[NBLK];
__device__ unsigned g_count = 0;

__device__ __forceinline__ float4 warp_red(float4 a) {
    #pragma unroll
    for (int off = 16; off > 0; off >>= 1) {
        a.x += __shfl_down_sync(0xffffffffu, a.x, off);
        a.y += __shfl_down_sync(0xffffffffu, a.y, off);
        a.z += __shfl_down_sync(0xffffffffu, a.z, off);
        a.w += __shfl_down_sync(0xffffffffu, a.w, off);
    }
    return a;
}

// Templated ONLY on the prediction-side level Q (compile-time HW for loads).
// Target-side level data stays runtime — the two flattenings disagree per block.
template<int Q>
__device__ __forceinline__ float4 body(
    const int tid, const int bid,
    const int b_img, const int lv_t, const float lmin, const float lmax,
    const float x, const float y,
    const float ymin_blk, const float ymax_blk,
    const float* __restrict__ cb, const float* __restrict__ rb, const float* __restrict__ ob,
    const float* __restrict__ boxes, const int* __restrict__ labels,
    float4* sbox, float* sarea, int* slab, int* s_n)
{
    constexpr int HW   = (Q == 0) ? 16384 : (Q == 1) ? 4096 : 1024;
    constexpr int QSH  = (Q == 0) ? 14 : (Q == 1) ? 12 : 10;      // log2(HW)
    constexpr int JOFF = (Q == 0) ? 0 : (Q == 1) ? 131072 : 163840;

    // ---- prediction-side decode: jl >= 0 guaranteed by dispatch on j0 ----
    const int jl  = (bid << 8) - JOFF;
    const int b_f = jl >> QSH;
    const int pix = (jl & (HW - 1)) + tid;

    const float* cptr = cb + (size_t)(b_f * NCLS) * HW + pix;

    // ---- prefetch 20 cls planes (immediate-offset LDG.32, all in flight) ----
    float v[NCLS];
    #pragma unroll
    for (int c = 0; c < NCLS; c++)
        v[c] = cptr[c * HW];

    // ---- box cull + stable compaction (warp 0; lv_t warp-uniform) ----
    if (tid < 32) {
        const float4 bb = reinterpret_cast<const float4*>(boxes)[b_img * 32 + tid];
        const float bw = bb.z - bb.x, bh = bb.w - bb.y;
        bool keep = (bb.y < ymax_blk) & (bb.w > ymin_blk);   // y-overlap
        if (lv_t == 0)      keep = keep & (bw <= 128.0f) & (bh <= 128.0f);
        else if (lv_t == 1) keep = keep & ((bw >= 64.0f)  | (bh >= 64.0f));
        else                keep = keep & ((bw >= 128.0f) | (bh >= 128.0f));
        const unsigned m = __ballot_sync(0xffffffffu, keep);
        if (keep) {
            const int idx = __popc(m & ((1u << tid) - 1u));   // stable order
            sbox[idx]  = bb;
            sarea[idx] = bw * bh;
            slab[idx]  = labels[b_img * 32 + tid];
        }
        if (tid == 0) *s_n = __popc(m);
    }
    __syncthreads();
    const int nbox = *s_n;

    // ---- box assignment over compacted survivors ----
    float best = INF_A;
    int   bi   = 0;
    for (int m = 0; m < nbox; m++) {
        const float4 bb = sbox[m];
        const float l  = x - bb.x;
        const float t  = y - bb.y;
        const float r  = bb.z - x;
        const float bo = bb.w - y;
        const float mn = fminf(fminf(l, t), fminf(r, bo));
        const float mx = fmaxf(fmaxf(l, t), fmaxf(r, bo));
        const bool ok = (mn > 0.0f) & (mx >= lmin) & (mx <= lmax);
        const float a = sarea[m];
        if (ok & (a < best)) { best = a; bi = m; }
    }
    const bool pos   = best < INF_A;
    const int  label = pos ? slab[bi] : -1;

    // ---- deferred reg/ctr loads: neg contributes exactly 0 to bbox/ctr ----
    const float* rp = rb + (size_t)(b_f * 4) * HW + pix;
    const float* op = ob + (size_t)b_f * HW + pix;
    float rg[4] = {0.f, 0.f, 0.f, 0.f};
    float oc    = 0.f;
    if (pos) {
        #pragma unroll
        for (int k = 0; k < 4; k++)
            rg[k] = rp[k * HW];
        oc = *op;
    }

    // ---- max logit (always needed: decides the ignore weight) ----
    float maxx = v[0];
    #pragma unroll
    for (int c = 1; c < NCLS; c++) maxx = fmaxf(maxx, v[c]);

    // ---- focal loss, EXACTLY gated: contributes only when pos or w==1.
    //      w = ((!pos) && maxx > ln(3/7)) ? 0 : 1, and focal enters the sum
    //      multiplied by w — so when the gate is false the entire 20-class
    //      computation is dead code. ~88% of threads (clustered into ~78%
    //      of warps) skip it. Bit-exact vs reference. ----
    float4 acc = make_float4(0.f, 0.f, 0.f, 0.f);
    if (pos | (maxx <= W_THRESH)) {
        float fsum = 0.0f;
        #pragma unroll
        for (int c = 0; c < NCLS; c++) {
            const float xx = v[c];
            const float E  = __expf(xx);
            const float u  = 1.0f + E;
            const float rc = __fdividef(1.0f, u);
            const float pp = E * rc;
            fsum += __log2f(u) * (pp * pp);
        }
        float f = fsum * LN2_075;
        if (pos) {
            // focal correction for the hit class (reload logit; cache hit)
            const float xl = cptr[label * HW];
            const float E  = __expf(xl);
            const float u  = 1.0f + E;
            const float rc = __fdividef(1.0f, u);
            const float pp = E * rc;
            const float sp = __logf(u);
            f += 0.25f * (sp - xl) * rc * rc - 0.75f * sp * pp * pp;
        }
        acc.x = f;
    }

    // ---- pos-only losses ----
    if (pos) {
        acc.w = 1.0f;

        // targets for winning box
        const float4 wb = sbox[bi];
        const float tl = x - wb.x, tt = y - wb.y, tr = wb.z - x, tb = wb.w - y;
        const float lrmin = fminf(tl, tr), lrmax = fmaxf(tl, tr);
        const float tbmin = fminf(tt, tb), tbmax = fmaxf(tt, tb);
        const float ratio = __fdividef(lrmin, fmaxf(lrmax, 1e-12f)) *
                            __fdividef(tbmin, fmaxf(tbmax, 1e-12f));
        const float ctr_t = sqrtf(fmaxf(ratio, 0.0f));

        // GIoU
        const float pl  = rg[0];
        const float pt2 = rg[1];
        const float pr  = rg[2];
        const float pb  = rg[3];
        const float t_area = (tl + tr) * (tt + tb);
        const float p_area = (pl + pr) * (pt2 + pb);
        const float w_i = fminf(pl, tl) + fminf(pr, tr);
        const float h_i = fminf(pb, tb) + fminf(pt2, tt);
        const float a_i = w_i * h_i;
        const float a_u = t_area + p_area - a_i;
        const float iou = __fdividef(a_i + 1.0f, a_u + 1.0f);
        const float gw  = fmaxf(pl, tl) + fmaxf(pr, tr);
        const float gh  = fmaxf(pb, tb) + fmaxf(pt2, tt);
        const float ac  = gw * gh;
        acc.y = (1.0f - (iou - __fdividef(ac - a_u, ac))) * ctr_t;

        // centerness BCE
        const float e2 = __expf(-fabsf(oc));
        acc.z = fmaxf(oc, 0.0f) + __logf(1.0f + e2) - oc * ctr_t;
    }
    return acc;
}

__global__ __launch_bounds__(256) void k_fused(
    const float* __restrict__ cls0, const float* __restrict__ cls1, const float* __restrict__ cls2,
    const float* __restrict__ reg0, const float* __restrict__ reg1, const float* __restrict__ reg2,
    const float* __restrict__ ctr0, const float* __restrict__ ctr1, const float* __restrict__ ctr2,
    const float* __restrict__ boxes, const int* __restrict__ labels,
    float* __restrict__ out)
{
    __shared__ float4 sbox[32];
    __shared__ float  sarea[32];
    __shared__ int    slab[32];
    __shared__ int    s_n;
    __shared__ float4 sw[8];
    __shared__ bool   s_last;

    const int tid = threadIdx.x;
    const int bid = blockIdx.x;

    // ---- target-side (batch-major) decode — INDEPENDENT of prediction side ----
    const int b_img = bid / BLKS_PER_IMG;
    const int pblk  = (bid - b_img * BLKS_PER_IMG) << 8;

    int lv_t, base, Wsh; float s, lmin, lmax;
    if (pblk < 16384)      { lv_t = 0; base = 0;     Wsh = 7; s = 4.0f;  lmin = -1.0f;  lmax = 64.0f;  }
    else if (pblk < 20480) { lv_t = 1; base = 16384; Wsh = 6; s = 8.0f;  lmin = 64.0f;  lmax = 128.0f; }
    else                   { lv_t = 2; base = 20480; Wsh = 5; s = 16.0f; lmin = 128.0f; lmax = INF_A;  }

    const int p0 = pblk + tid - base;
    const int hh = p0 >> Wsh;
    const int ww = p0 & ((1 << Wsh) - 1);
    const float x = ww * s + 0.5f * s;
    const float y = hh * s + 0.5f * s;

    const int lo_blk = pblk - base;
    const float ymin_blk = (float)(lo_blk >> Wsh) * s + 0.5f * s;
    const float ymax_blk = (float)((lo_blk + 255) >> Wsh) * s + 0.5f * s;

    // ---- dispatch on PREDICTION-side level (j0 thresholds) ----
    const int j0 = bid << 8;
    float4 acc;
    if (j0 < 131072)
        acc = body<0>(tid, bid, b_img, lv_t, lmin, lmax, x, y, ymin_blk, ymax_blk,
                      cls0, reg0, ctr0, boxes, labels, sbox, sarea, slab, &s_n);
    else if (j0 < 163840)
        acc = body<1>(tid, bid, b_img, lv_t, lmin, lmax, x, y, ymin_blk, ymax_blk,
                      cls1, reg1, ctr1, boxes, labels, sbox, sarea, slab, &s_n);
    else
        acc = body<2>(tid, bid, b_img, lv_t, lmin, lmax, x, y, ymin_blk, ymax_blk,
                      cls2, reg2, ctr2, boxes, labels, sbox, sarea, slab, &s_n);

    // ---- block reduction (8 warps) -> per-block partial ----
    acc = warp_red(acc);
    if ((tid & 31) == 0) sw[tid >> 5] = acc;
    __syncthreads();
    if (tid < 32) {
        float4 a = (tid < 8) ? sw[tid] : make_float4(0.f, 0.f, 0.f, 0.f);
        #pragma unroll
        for (int off = 4; off > 0; off >>= 1) {
            a.x += __shfl_down_sync(0xffffffffu, a.x, off);
            a.y += __shfl_down_sync(0xffffffffu, a.y, off);
            a.z += __shfl_down_sync(0xffffffffu, a.z, off);
            a.w += __shfl_down_sync(0xffffffffu, a.w, off);
        }
        if (tid == 0) g_part[bid] = a;
    }

    // ---- last block finalizes ----
    if (tid == 0) {
        __threadfence();
        unsigned old = atomicAdd(&g_count, 1u);
        s_last = (old == (unsigned)(gridDim.x - 1));
    }
    __syncthreads();
    if (!s_last) return;
    __threadfence();

    float4 a = make_float4(0.f, 0.f, 0.f, 0.f);
    for (int i = tid; i < NBLK; i += 256) {
        const float4* pp = &g_part[i];
        float4 vv;
        asm volatile("ld.global.cg.v4.f32 {%0,%1,%2,%3}, [%4];"
                     : "=f"(vv.x), "=f"(vv.y), "=f"(vv.z), "=f"(vv.w) : "l"(pp));
        a.x += vv.x; a.y += vv.y; a.z += vv.z; a.w += vv.w;
    }
    a = warp_red(a);
    if ((tid & 31) == 0) sw[tid >> 5] = a;
    __syncthreads();
    if (tid == 0) {
        float sx = 0.f, sy = 0.f, sz = 0.f, np = 0.f;
        #pragma unroll
        for (int k = 0; k < 8; k++) { sx += sw[k].x; sy += sw[k].y; sz += sw[k].z; np += sw[k].w; }
        const float inv = __fdividef(1.0f, fmaxf(np, 1.0f));
        out[0] = sx * inv;
        out[1] = sy * inv;
        out[2] = sz * inv;
        g_count = 0;   // reset for next graph replay
    }
}

extern "C" void kernel_launch(void* const* d_in, const int* in_sizes, int n_in,
                              void* d_out, int out_size) {
    const float *cls0, *cls1, *cls2, *reg0, *reg1, *reg2, *ctr0, *ctr1, *ctr2;
    if (in_sizes[1] == 655360) {   // reference-signature order
        cls0 = (const float*)d_in[0]; cls1 = (const float*)d_in[1]; cls2 = (const float*)d_in[2];
        reg0 = (const float*)d_in[3]; reg1 = (const float*)d_in[4]; reg2 = (const float*)d_in[5];
        ctr0 = (const float*)d_in[6]; ctr1 = (const float*)d_in[7]; ctr2 = (const float*)d_in[8];
    } else {                       // setup_inputs dict order
        cls0 = (const float*)d_in[0]; reg0 = (const float*)d_in[1]; ctr0 = (const float*)d_in[2];
        cls1 = (const float*)d_in[3]; reg1 = (const float*)d_in[4]; ctr1 = (const float*)d_in[5];
        cls2 = (const float*)d_in[6]; reg2 = (const float*)d_in[7]; ctr2 = (const float*)d_in[8];
    }
    const float* boxes  = (const float*)d_in[9];
    const int*   labels = (const int*)d_in[10];

    k_fused<<<NBLK, 256>>>(cls0, cls1, cls2, reg0, reg1, reg2,
                           ctr0, ctr1, ctr2, boxes, labels, (float*)d_out);
}

// round 13
// speedup vs baseline: 1.7485x; 1.1606x over previous
#include <cuda_runtime.h>
#include <math.h>

#define TOTAL_PTS    172032
#define NBLK         672          // blocks; 256 threads x 1 pt = 256 pts/block
#define BLKS_PER_IMG 84           // 21504 / 256
#define INF_A        1.0e8f
#define NCLS         20
#define LN2_075      0.5198603854199589f     // 0.75 * ln(2)
#define W_THRESH     -0.8472978603872037f    // ln(0.3/0.7)

__device__ float4   g_part[NBLK];
__device__ unsigned g_count = 0;

__device__ __forceinline__ float4 warp_red(float4 a) {
    #pragma unroll
    for (int off = 16; off > 0; off >>= 1) {
        a.x += __shfl_down_sync(0xffffffffu, a.x, off);
        a.y += __shfl_down_sync(0xffffffffu, a.y, off);
        a.z += __shfl_down_sync(0xffffffffu, a.z, off);
        a.w += __shfl_down_sync(0xffffffffu, a.w, off);
    }
    return a;
}

// Templated ONLY on the prediction-side level Q (compile-time HW for loads).
// Target-side level data stays runtime — the two flattenings disagree per block.
template<int Q>
__device__ __forceinline__ float4 body(
    const int tid, const int bid,
    const int b_img, const int lv_t, const float lmin, const float lmax,
    const float x, const float y,
    const float ymin_blk, const float ymax_blk,
    const float* __restrict__ cb, const float* __restrict__ rb, const float* __restrict__ ob,
    const float* __restrict__ boxes, const int* __restrict__ labels,
    float4* sbox, float* sarea, int* slab, int* s_n)
{
    constexpr int HW   = (Q == 0) ? 16384 : (Q == 1) ? 4096 : 1024;
    constexpr int QSH  = (Q == 0) ? 14 : (Q == 1) ? 12 : 10;      // log2(HW)
    constexpr int JOFF = (Q == 0) ? 0 : (Q == 1) ? 131072 : 163840;

    // ---- prediction-side decode: jl >= 0 guaranteed by dispatch on j0 ----
    const int jl  = (bid << 8) - JOFF;
    const int b_f = jl >> QSH;
    const int pix = (jl & (HW - 1)) + tid;

    const float* cptr = cb + (size_t)(b_f * NCLS) * HW + pix;

    // ---- STAGE 1: prefetch only cls planes 0..3 ----
    float v[NCLS];
    #pragma unroll
    for (int c = 0; c < 4; c++)
        v[c] = cptr[c * HW];

    // ---- box cull + stable compaction (warp 0; lv_t warp-uniform) ----
    if (tid < 32) {
        const float4 bb = reinterpret_cast<const float4*>(boxes)[b_img * 32 + tid];
        const float bw = bb.z - bb.x, bh = bb.w - bb.y;
        bool keep = (bb.y < ymax_blk) & (bb.w > ymin_blk);   // y-overlap
        if (lv_t == 0)      keep = keep & (bw <= 128.0f) & (bh <= 128.0f);
        else if (lv_t == 1) keep = keep & ((bw >= 64.0f)  | (bh >= 64.0f));
        else                keep = keep & ((bw >= 128.0f) | (bh >= 128.0f));
        const unsigned m = __ballot_sync(0xffffffffu, keep);
        if (keep) {
            const int idx = __popc(m & ((1u << tid) - 1u));   // stable order
            sbox[idx]  = bb;
            sarea[idx] = bw * bh;
            slab[idx]  = labels[b_img * 32 + tid];
        }
        if (tid == 0) *s_n = __popc(m);
    }
    __syncthreads();
    const int nbox = *s_n;

    // ---- box assignment over compacted survivors ----
    float best = INF_A;
    int   bi   = 0;
    for (int m = 0; m < nbox; m++) {
        const float4 bb = sbox[m];
        const float l  = x - bb.x;
        const float t  = y - bb.y;
        const float r  = bb.z - x;
        const float bo = bb.w - y;
        const float mn = fminf(fminf(l, t), fminf(r, bo));
        const float mx = fmaxf(fmaxf(l, t), fmaxf(r, bo));
        const bool ok = (mn > 0.0f) & (mx >= lmin) & (mx <= lmax);
        const float a = sarea[m];
        if (ok & (a < best)) { best = a; bi = m; }
    }
    const bool pos   = best < INF_A;
    const int  label = pos ? slab[bi] : -1;

    // ---- ignore-weight early exit (bit-exact):
    //      A negative point contributes ONLY if its max logit <= ln(3/7).
    //      P(one logit > T) = 0.80, so after 4 planes a neg lane is decided
    //      with P = 1 - 0.2^4 = 0.9984. If NO lane in the warp is pos or
    //      undecided, every lane has w = 0 -> zero contribution; skip the
    //      remaining 16 plane loads + all focal work for the whole warp. ----
    float m4 = fmaxf(fmaxf(v[0], v[1]), fmaxf(v[2], v[3]));
    const bool need = pos | (m4 <= W_THRESH);

    float4 acc = make_float4(0.f, 0.f, 0.f, 0.f);
    if (__any_sync(0xffffffffu, need)) {
        // ---- STAGE 2: remaining 16 cls planes (whole warp; same cachelines) ----
        #pragma unroll
        for (int c = 4; c < NCLS; c++)
            v[c] = cptr[c * HW];

        // ---- deferred reg/ctr loads (pos lanes only need them) ----
        const float* rp = rb + (size_t)(b_f * 4) * HW + pix;
        const float* op = ob + (size_t)b_f * HW + pix;
        float rg[4] = {0.f, 0.f, 0.f, 0.f};
        float oc    = 0.f;
        if (pos) {
            #pragma unroll
            for (int k = 0; k < 4; k++)
                rg[k] = rp[k * HW];
            oc = *op;
        }

        float maxx = m4;
        #pragma unroll
        for (int c = 4; c < NCLS; c++) maxx = fmaxf(maxx, v[c]);

        // ---- focal, exactly gated per lane ----
        if (pos | (maxx <= W_THRESH)) {
            float fsum = 0.0f;
            #pragma unroll
            for (int c = 0; c < NCLS; c++) {
                const float xx = v[c];
                const float E  = __expf(xx);
                const float u  = 1.0f + E;
                const float rc = __fdividef(1.0f, u);
                const float pp = E * rc;
                fsum += __log2f(u) * (pp * pp);
            }
            float f = fsum * LN2_075;
            if (pos) {
                // focal correction for the hit class (reload logit; cache hit)
                const float xl = cptr[label * HW];
                const float E  = __expf(xl);
                const float u  = 1.0f + E;
                const float rc = __fdividef(1.0f, u);
                const float pp = E * rc;
                const float sp = __logf(u);
                f += 0.25f * (sp - xl) * rc * rc - 0.75f * sp * pp * pp;
            }
            acc.x = f;
        }

        // ---- pos-only losses ----
        if (pos) {
            acc.w = 1.0f;

            // targets for winning box
            const float4 wb = sbox[bi];
            const float tl = x - wb.x, tt = y - wb.y, tr = wb.z - x, tb = wb.w - y;
            const float lrmin = fminf(tl, tr), lrmax = fmaxf(tl, tr);
            const float tbmin = fminf(tt, tb), tbmax = fmaxf(tt, tb);
            const float ratio = __fdividef(lrmin, fmaxf(lrmax, 1e-12f)) *
                                __fdividef(tbmin, fmaxf(tbmax, 1e-12f));
            const float ctr_t = sqrtf(fmaxf(ratio, 0.0f));

            // GIoU
            const float pl  = rg[0];
            const float pt2 = rg[1];
            const float pr  = rg[2];
            const float pb  = rg[3];
            const float t_area = (tl + tr) * (tt + tb);
            const float p_area = (pl + pr) * (pt2 + pb);
            const float w_i = fminf(pl, tl) + fminf(pr, tr);
            const float h_i = fminf(pb, tb) + fminf(pt2, tt);
            const float a_i = w_i * h_i;
            const float a_u = t_area + p_area - a_i;
            const float iou = __fdividef(a_i + 1.0f, a_u + 1.0f);
            const float gw  = fmaxf(pl, tl) + fmaxf(pr, tr);
            const float gh  = fmaxf(pb, tb) + fmaxf(pt2, tt);
            const float ac  = gw * gh;
            acc.y = (1.0f - (iou - __fdividef(ac - a_u, ac))) * ctr_t;

            // centerness BCE
            const float e2 = __expf(-fabsf(oc));
            acc.z = fmaxf(oc, 0.0f) + __logf(1.0f + e2) - oc * ctr_t;
        }
    }
    return acc;
}

__global__ __launch_bounds__(256) void k_fused(
    const float* __restrict__ cls0, const float* __restrict__ cls1, const float* __restrict__ cls2,
    const float* __restrict__ reg0, const float* __restrict__ reg1, const float* __restrict__ reg2,
    const float* __restrict__ ctr0, const float* __restrict__ ctr1, const float* __restrict__ ctr2,
    const float* __restrict__ boxes, const int* __restrict__ labels,
    float* __restrict__ out)
{
    __shared__ float4 sbox[32];
    __shared__ float  sarea[32];
    __shared__ int    slab[32];
    __shared__ int    s_n;
    __shared__ float4 sw[8];
    __shared__ bool   s_last;

    const int tid = threadIdx.x;
    const int bid = blockIdx.x;

    // ---- target-side (batch-major) decode — INDEPENDENT of prediction side ----
    const int b_img = bid / BLKS_PER_IMG;
    const int pblk  = (bid - b_img * BLKS_PER_IMG) << 8;

    int lv_t, base, Wsh; float s, lmin, lmax;
    if (pblk < 16384)      { lv_t = 0; base = 0;     Wsh = 7; s = 4.0f;  lmin = -1.0f;  lmax = 64.0f;  }
    else if (pblk < 20480) { lv_t = 1; base = 16384; Wsh = 6; s = 8.0f;  lmin = 64.0f;  lmax = 128.0f; }
    else                   { lv_t = 2; base = 20480; Wsh = 5; s = 16.0f; lmin = 128.0f; lmax = INF_A;  }

    const int p0 = pblk + tid - base;
    const int hh = p0 >> Wsh;
    const int ww = p0 & ((1 << Wsh) - 1);
    const float x = ww * s + 0.5f * s;
    const float y = hh * s + 0.5f * s;

    const int lo_blk = pblk - base;
    const float ymin_blk = (float)(lo_blk >> Wsh) * s + 0.5f * s;
    const float ymax_blk = (float)((lo_blk + 255) >> Wsh) * s + 0.5f * s;

    // ---- dispatch on PREDICTION-side level (j0 thresholds) ----
    const int j0 = bid << 8;
    float4 acc;
    if (j0 < 131072)
        acc = body<0>(tid, bid, b_img, lv_t, lmin, lmax, x, y, ymin_blk, ymax_blk,
                      cls0, reg0, ctr0, boxes, labels, sbox, sarea, slab, &s_n);
    else if (j0 < 163840)
        acc = body<1>(tid, bid, b_img, lv_t, lmin, lmax, x, y, ymin_blk, ymax_blk,
                      cls1, reg1, ctr1, boxes, labels, sbox, sarea, slab, &s_n);
    else
        acc = body<2>(tid, bid, b_img, lv_t, lmin, lmax, x, y, ymin_blk, ymax_blk,
                      cls2, reg2, ctr2, boxes, labels, sbox, sarea, slab, &s_n);

    // ---- block reduction (8 warps) -> per-block partial ----
    acc = warp_red(acc);
    if ((tid & 31) == 0) sw[tid >> 5] = acc;
    __syncthreads();
    if (tid < 32) {
        float4 a = (tid < 8) ? sw[tid] : make_float4(0.f, 0.f, 0.f, 0.f);
        #pragma unroll
        for (int off = 4; off > 0; off >>= 1) {
            a.x += __shfl_down_sync(0xffffffffu, a.x, off);
            a.y += __shfl_down_sync(0xffffffffu, a.y, off);
            a.z += __shfl_down_sync(0xffffffffu, a.z, off);
            a.w += __shfl_down_sync(0xffffffffu, a.w, off);
        }
        if (tid == 0) g_part[bid] = a;
    }

    // ---- last block finalizes ----
    if (tid == 0) {
        __threadfence();
        unsigned old = atomicAdd(&g_count, 1u);
        s_last = (old == (unsigned)(gridDim.x - 1));
    }
    __syncthreads();
    if (!s_last) return;
    __threadfence();

    float4 a = make_float4(0.f, 0.f, 0.f, 0.f);
    for (int i = tid; i < NBLK; i += 256) {
        const float4* pp = &g_part[i];
        float4 vv;
        asm volatile("ld.global.cg.v4.f32 {%0,%1,%2,%3}, [%4];"
                     : "=f"(vv.x), "=f"(vv.y), "=f"(vv.z), "=f"(vv.w) : "l"(pp));
        a.x += vv.x; a.y += vv.y; a.z += vv.z; a.w += vv.w;
    }
    a = warp_red(a);
    if ((tid & 31) == 0) sw[tid >> 5] = a;
    __syncthreads();
    if (tid == 0) {
        float sx = 0.f, sy = 0.f, sz = 0.f, np = 0.f;
        #pragma unroll
        for (int k = 0; k < 8; k++) { sx += sw[k].x; sy += sw[k].y; sz += sw[k].z; np += sw[k].w; }
        const float inv = __fdividef(1.0f, fmaxf(np, 1.0f));
        out[0] = sx * inv;
        out[1] = sy * inv;
        out[2] = sz * inv;
        g_count = 0;   // reset for next graph replay
    }
}

extern "C" void kernel_launch(void* const* d_in, const int* in_sizes, int n_in,
                              void* d_out, int out_size) {
    const float *cls0, *cls1, *cls2, *reg0, *reg1, *reg2, *ctr0, *ctr1, *ctr2;
    if (in_sizes[1] == 655360) {   // reference-signature order
        cls0 = (const float*)d_in[0]; cls1 = (const float*)d_in[1]; cls2 = (const float*)d_in[2];
        reg0 = (const float*)d_in[3]; reg1 = (const float*)d_in[4]; reg2 = (const float*)d_in[5];
        ctr0 = (const float*)d_in[6]; ctr1 = (const float*)d_in[7]; ctr2 = (const float*)d_in[8];
    } else {                       // setup_inputs dict order
        cls0 = (const float*)d_in[0]; reg0 = (const float*)d_in[1]; ctr0 = (const float*)d_in[2];
        cls1 = (const float*)d_in[3]; reg1 = (const float*)d_in[4]; ctr1 = (const float*)d_in[5];
        cls2 = (const float*)d_in[6]; reg2 = (const float*)d_in[7]; ctr2 = (const float*)d_in[8];
    }
    const float* boxes  = (const float*)d_in[9];
    const int*   labels = (const int*)d_in[10];

    k_fused<<<NBLK, 256>>>(cls0, cls1, cls2, reg0, reg1, reg2,
                           ctr0, ctr1, ctr2, boxes, labels, (float*)d_out);
}